// round 10
// baseline (speedup 1.0000x reference)
#include <cuda_runtime.h>
#include <cuda_fp16.h>

#define DIMN   200
#define LEN    256
#define BATCH  8
#define NTOK   (BATCH*LEN)      // 2048
#define D2     (2*DIMN)         // 400

// ---------------- scratch (static device memory; no allocations) ----------------
__device__ float  g_h    [NTOK*DIMN + 64];   // h, padded for attn e-overread
__device__ float  g_h1m  [NTOK*DIMN + 64];   // (h1+b)/c, mask-encoded (1e30), padded
__device__ float2 g_hpack[NTOK*DIMN + 64];   // {h2/c mask-encoded, h}, padded
__device__ float  g_hf2c [NTOK*DIMN];        // h @ Wf2_w + Wf2_b
__device__ float  g_sfw  [NTOK*DIMN];
__device__ float  g_sbw  [NTOK*DIMN];
__device__ float  g_hsumP[128*DIMN + 64];    // per-16-token-tile partial sums of h
__device__ float  g_uu   [NTOK*D2];          // [token][2D]
__device__ float  g_tmp  [NTOK*D2];          // elu(uu@Ws1+b)
__device__ float  g_part2[128*D2];           // per-Mtile partial of s_s

__device__ __forceinline__ float eluf(float a){ return a > 0.0f ? a : expm1f(a); }
__device__ __forceinline__ __half2 hw_tanh2(__half2 x){
    __half2 y; asm("tanh.approx.f16x2 %0, %1;" : "=r"(*(unsigned*)&y) : "r"(*(unsigned*)&x)); return y;
}
__device__ __forceinline__ __half2 hw_ex22(__half2 x){
    __half2 y; asm("ex2.approx.f16x2 %0, %1;" : "=r"(*(unsigned*)&y) : "r"(*(unsigned*)&x)); return y;
}
__device__ __forceinline__ unsigned f2tf32(float x){
    unsigned y; asm("cvt.rna.tf32.f32 %0, %1;" : "=r"(y) : "f"(x)); return y;
}
__device__ __forceinline__ void mma_tf32(float c[4],
    unsigned a0, unsigned a1, unsigned a2, unsigned a3,
    unsigned b0, unsigned b1)
{
    asm volatile(
        "mma.sync.aligned.m16n8k8.row.col.f32.tf32.tf32.f32 "
        "{%0,%1,%2,%3}, {%4,%5,%6,%7}, {%8,%9}, {%0,%1,%2,%3};"
        : "+f"(c[0]), "+f"(c[1]), "+f"(c[2]), "+f"(c[3])
        : "r"(a0), "r"(a1), "r"(a2), "r"(a3), "r"(b0), "r"(b1));
}

// ==== 3xTF32 tensor-core GEMM (BM=16, BN=64, single-buffered, 128 thr = 4 warps) ====
// warp w covers 16 cols (2 m16n8k8 n-tiles); m16 spans the whole BM.
// x = hi + lo (both tf32); C += lo*hi_B + hi*lo_B + hi*hi_B  -> ~fp32 accuracy.
// Accumulators remapped through Cs so the validated elementwise epilogues survive.
// MODE 0: h   = elu(gather(emb,x) @ Wh + Wh_b)                      -> g_h
// MODE 1: y<12: {W1(+batt,mask,/c), W2(mask,/c,pack h), Wf2(+b)};  y==12: hsum partials
// MODE 2: f = sigmoid(s_dir @ Wf1 + hf2c); uu = f*h+(1-f)*s         -> g_uu (dir=blockIdx.z)
// MODE 3: tmp = elu(uu @ Ws1 + Ws1_b)                               -> g_tmp
// MODE 4: att_s = tmp @ Ws + Ws_b; partial s_s = sum_rows uu*att_s  -> g_part2
#define BM 16
#define BN 64

template<int MODE, int K, int N, int BKT>
__global__ void __launch_bounds__(128) gemm_k(
    const float* __restrict__ A,
    const float* __restrict__ B0, const float* __restrict__ B1, const float* __restrict__ B2,
    const float* __restrict__ bias0, const float* __restrict__ bias2,
    const int* __restrict__ xidx, const float* __restrict__ emb,
    const float* __restrict__ cptr)
{
    const int tid = threadIdx.x;
    const int t0  = blockIdx.x * BM;

    // ---- hsum side-channel slice (MODE 1, y==12) ----
    if (MODE == 1 && blockIdx.y == 12) {
        for (int e = tid; e < DIMN; e += 128) {
            float s = 0.0f;
            #pragma unroll 4
            for (int j = 0; j < BM; ++j) s += g_h[(t0 + j)*DIMN + e];
            g_hsumP[blockIdx.x*DIMN + e] = s;
        }
        return;
    }

    constexpr int PA = 25;   // A smem pad (conflict-tuned)
    constexpr int PB = 72;   // B smem pad (72 % 32 == 8 -> disjoint frag banks)

    __shared__ unsigned Ash[BKT][PA], Asl[BKT][PA];
    __shared__ unsigned Bsh[BKT][PB], Bsl[BKT][PB];
    __shared__ float    Cs[BM][BN];
    __shared__ float    red[8][BN];

    const int tx   = tid & 15;      // epilogue cols tx*4
    const int ty   = tid >> 4;      // epilogue rows ty*2
    const int lane = tid & 31;
    const int wrp  = tid >> 5;      // 0..3 -> 16-col slice
    const int gq = lane >> 2;       // groupID 0..7
    const int qq = lane & 3;        // threadID_in_group 0..3

    int n0, matid = 0;
    const float* B = B0;
    if (MODE == 1) {
        matid = blockIdx.y >> 2;
        n0 = (blockIdx.y & 3) * BN;
        B  = (matid == 0) ? B0 : (matid == 1) ? B1 : B2;
    } else {
        n0 = blockIdx.y * BN;
    }

    const float* Asrc;
    if      (MODE == 0) Asrc = A;
    else if (MODE == 1) Asrc = g_h;
    else if (MODE == 2) Asrc = blockIdx.z ? g_sbw : g_sfw;
    else if (MODE == 3) Asrc = g_uu;
    else                Asrc = g_tmp;

    // staging maps: A 16xBKT (1 float4/thread per 32-k), B BKTx64 (4 float4/thread)
    const int am  = tid >> 3;           // 0..15
    const int ak  = (tid & 7) * 4;      // 0..28
    const int bk  = tid >> 4;           // 0..7 (+8r)
    const int bn  = (tid & 15) * 4;     // 0..60

    long arow;
    if (MODE == 0) arow = (long)__ldg(&xidx[t0 + am]) * K;
    else           arow = (long)(t0 + am) * K;

    const int gn_b = n0 + bn;
    const bool bvalid = (gn_b < N);

    float cacc[2][4];
    #pragma unroll
    for (int t = 0; t < 2; t++)
        #pragma unroll
        for (int j = 0; j < 4; j++) cacc[t][j] = 0.0f;

    float4 av, bv[4];
    auto loadTile = [&](int k0) {
        int kq = k0 + ak;
        av = make_float4(0,0,0,0);
        if (K % BKT == 0 || kq < K)      // K%4==0 so float4-granular guard is exact
            av = *reinterpret_cast<const float4*>(Asrc + arow + kq);
        #pragma unroll
        for (int r = 0; r < 4; r++) {
            int kr = k0 + bk + r*8;
            bv[r] = make_float4(0,0,0,0);
            if (bvalid && (K % BKT == 0 || kr < K))
                bv[r] = *reinterpret_cast<const float4*>(B + (long)kr * N + gn_b);
        }
    };
    auto splitStore = [&](unsigned* hp, unsigned* lp, float v) {
        unsigned h = f2tf32(v);
        *hp = h;
        *lp = f2tf32(v - __uint_as_float(h));
    };
    auto storeTile = [&]() {
        const float va[4] = {av.x, av.y, av.z, av.w};
        #pragma unroll
        for (int q = 0; q < 4; q++)
            splitStore(&Ash[ak+q][am], &Asl[ak+q][am], va[q]);
        #pragma unroll
        for (int r = 0; r < 4; r++) {
            int kr = bk + r*8;
            const float vb[4] = {bv[r].x, bv[r].y, bv[r].z, bv[r].w};
            #pragma unroll
            for (int q = 0; q < 4; q++)
                splitStore(&Bsh[kr][bn+q], &Bsl[kr][bn+q], vb[q]);
        }
    };

    loadTile(0);
    for (int k0 = 0; k0 < K; k0 += BKT) {
        storeTile();
        __syncthreads();
        const bool more = (k0 + BKT < K);
        if (more) loadTile(k0 + BKT);

        #pragma unroll
        for (int ks = 0; ks < BKT; ks += 8) {
            unsigned ah0 = Ash[ks+qq  ][gq  ], ah1 = Ash[ks+qq  ][gq+8];
            unsigned ah2 = Ash[ks+qq+4][gq  ], ah3 = Ash[ks+qq+4][gq+8];
            unsigned al0 = Asl[ks+qq  ][gq  ], al1 = Asl[ks+qq  ][gq+8];
            unsigned al2 = Asl[ks+qq+4][gq  ], al3 = Asl[ks+qq+4][gq+8];
            #pragma unroll
            for (int t = 0; t < 2; t++) {
                int col = wrp*16 + t*8 + gq;
                unsigned bh0 = Bsh[ks+qq  ][col];
                unsigned bh1 = Bsh[ks+qq+4][col];
                unsigned bl0 = Bsl[ks+qq  ][col];
                unsigned bl1 = Bsl[ks+qq+4][col];
                mma_tf32(cacc[t], al0, al1, al2, al3, bh0, bh1);
                mma_tf32(cacc[t], ah0, ah1, ah2, ah3, bl0, bl1);
                mma_tf32(cacc[t], ah0, ah1, ah2, ah3, bh0, bh1);
            }
        }
        __syncthreads();
    }

    // ---- remap accumulators to (ty,tx) 2x4 ownership via Cs ----
    #pragma unroll
    for (int t = 0; t < 2; t++) {
        int n = wrp*16 + t*8 + 2*qq;
        Cs[gq  ][n  ] = cacc[t][0];
        Cs[gq  ][n+1] = cacc[t][1];
        Cs[gq+8][n  ] = cacc[t][2];
        Cs[gq+8][n+1] = cacc[t][3];
    }
    __syncthreads();
    float acc[2][4];
    #pragma unroll
    for (int i = 0; i < 2; i++)
        #pragma unroll
        for (int j = 0; j < 4; j++)
            acc[i][j] = Cs[ty*2 + i][tx*4 + j];

    // ---------------- epilogues (elementwise logic unchanged; 2-row ownership) ----
    int  gcv[4]; bool ok[4]; float bj[4];
    #pragma unroll
    for (int j = 0; j < 4; j++) {
        gcv[j] = n0 + tx*4 + j;
        ok[j]  = gcv[j] < N;
    }

    if (MODE == 0) {
        #pragma unroll
        for (int j = 0; j < 4; j++) bj[j] = ok[j] ? __ldg(&bias0[gcv[j]]) : 0.0f;
        #pragma unroll
        for (int i = 0; i < 2; i++) {
            int gt = t0 + ty*2 + i;
            #pragma unroll
            for (int j = 0; j < 4; j++)
                if (ok[j]) g_h[gt*DIMN + gcv[j]] = eluf(acc[i][j] + bj[j]);
        }
    }
    else if (MODE == 1) {
        const float invc = 1.0f / __ldg(cptr);
        #pragma unroll
        for (int j = 0; j < 4; j++) {
            bj[j] = 0.0f;
            if (ok[j]) {
                if (matid == 0) bj[j] = __ldg(&bias0[gcv[j]]);
                if (matid == 2) bj[j] = __ldg(&bias2[gcv[j]]);
            }
        }
        #pragma unroll
        for (int i = 0; i < 2; i++) {
            int gt = t0 + ty*2 + i;
            long eoff = (long)__ldg(&xidx[gt]) * DIMN;
            #pragma unroll
            for (int j = 0; j < 4; j++) {
                if (!ok[j]) continue;
                if (matid == 0) {
                    bool mk = (__ldg(&emb[eoff + gcv[j]]) == 1.0f);
                    g_h1m[gt*DIMN + gcv[j]] = mk ? 1e30f : (acc[i][j] + bj[j]) * invc;
                } else if (matid == 1) {
                    bool mk = (__ldg(&emb[eoff + gcv[j]]) == 1.0f);
                    float2 pp;
                    pp.x = mk ? 1e30f : acc[i][j] * invc;
                    pp.y = g_h[gt*DIMN + gcv[j]];
                    g_hpack[gt*DIMN + gcv[j]] = pp;
                } else {
                    g_hf2c[gt*DIMN + gcv[j]] = acc[i][j] + bj[j];
                }
            }
        }
    }
    else if (MODE == 2) {
        const int dir = blockIdx.z;
        #pragma unroll
        for (int i = 0; i < 2; i++) {
            int gt = t0 + ty*2 + i;
            #pragma unroll
            for (int j = 0; j < 4; j++) {
                if (!ok[j]) continue;
                int idx = gt*DIMN + gcv[j];
                float f = 1.0f / (1.0f + __expf(-(acc[i][j] + g_hf2c[idx])));
                float hh = g_h[idx];
                float ss = Asrc[idx];
                g_uu[gt*D2 + dir*DIMN + gcv[j]] = f*hh + (1.0f - f)*ss;
            }
        }
    }
    else if (MODE == 3) {
        #pragma unroll
        for (int j = 0; j < 4; j++) bj[j] = ok[j] ? __ldg(&bias0[gcv[j]]) : 0.0f;
        #pragma unroll
        for (int i = 0; i < 2; i++) {
            int gt = t0 + ty*2 + i;
            #pragma unroll
            for (int j = 0; j < 4; j++)
                if (ok[j]) g_tmp[gt*D2 + gcv[j]] = eluf(acc[i][j] + bj[j]);
        }
    }
    else { // MODE 4
        #pragma unroll
        for (int j = 0; j < 4; j++) bj[j] = ok[j] ? __ldg(&bias0[gcv[j]]) : 0.0f;
        float pr[4] = {0,0,0,0};
        #pragma unroll
        for (int i = 0; i < 2; i++) {
            int gt = t0 + ty*2 + i;
            #pragma unroll
            for (int j = 0; j < 4; j++) {
                if (!ok[j]) continue;
                float att = acc[i][j] + bj[j];
                pr[j] += g_uu[gt*D2 + gcv[j]] * att;
            }
        }
        #pragma unroll
        for (int j = 0; j < 4; j++) red[ty][tx*4 + j] = pr[j];
        __syncthreads();
        if (tid < BN) {
            float s = 0.0f;
            #pragma unroll
            for (int r = 0; r < 8; r++) s += red[r][tid];
            int gc = n0 + tid;
            if (gc < N) g_part2[blockIdx.x*D2 + gc] = s;
        }
    }
}

// ======================= fused masked per-feature softmax attention ============
// block = (b, group of 4 l). thread = feature e. f16x2 MUFU (1 MUFU/element).
__global__ void __launch_bounds__(224) attn_kernel(const float* __restrict__ cptr)
{
    const int b  = blockIdx.y;
    const int l0 = blockIdx.x * 4;
    const int e  = threadIdx.x;

    const float C  = __ldg(cptr);
    const float ktf = C * 1.4426950408889634f;   // c*log2(e)
    const __half2 kt2 = __float2half2_rn(ktf);

    float h1s[4];
    #pragma unroll
    for (int i = 0; i < 4; i++) h1s[i] = g_h1m[(b*LEN + l0 + i)*DIMN + e];

    float denf[4] = {0,0,0,0}, numf[4] = {0,0,0,0};
    float denb[4] = {0,0,0,0}, numb[4] = {0,0,0,0};

    const float2* __restrict__ hp = g_hpack + (size_t)b*LEN*DIMN + e;

    // ---- m < l0 : backward for all 4 ----
    #pragma unroll 2
    for (int m = 0; m < l0; ++m) {
        float2 pv = __ldg(hp + m*DIMN);
        float zc[4];
        #pragma unroll
        for (int i = 0; i < 4; i++) zc[i] = h1s[i] + pv.x;
        __half2 wa = hw_ex22(__hmul2(hw_tanh2(__floats2half2_rn(zc[0], zc[1])), kt2));
        __half2 wb = hw_ex22(__hmul2(hw_tanh2(__floats2half2_rn(zc[2], zc[3])), kt2));
        float2 w01 = __half22float2(wa), w23 = __half22float2(wb);
        float w[4] = {w01.x, w01.y, w23.x, w23.y};
        #pragma unroll
        for (int i = 0; i < 4; i++) {
            float wi = (zc[i] < 1e29f) ? w[i] : 0.0f;
            denb[i] += wi;
            numb[i] = fmaf(wi, pv.y, numb[i]);
        }
    }
    // ---- edge iterations m = l0..l0+3 ----
    #pragma unroll
    for (int i2 = 0; i2 < 4; i2++) {
        float2 pv = __ldg(hp + (l0 + i2)*DIMN);
        float zc[4];
        #pragma unroll
        for (int i = 0; i < 4; i++) zc[i] = h1s[i] + pv.x;
        __half2 wa = hw_ex22(__hmul2(hw_tanh2(__floats2half2_rn(zc[0], zc[1])), kt2));
        __half2 wb = hw_ex22(__hmul2(hw_tanh2(__floats2half2_rn(zc[2], zc[3])), kt2));
        float2 w01 = __half22float2(wa), w23 = __half22float2(wb);
        float w[4] = {w01.x, w01.y, w23.x, w23.y};
        #pragma unroll
        for (int i = 0; i < 4; i++) {
            if (i == i2) continue;
            float wi = (zc[i] < 1e29f) ? w[i] : 0.0f;
            if (i < i2) { denf[i] += wi; numf[i] = fmaf(wi, pv.y, numf[i]); }
            else        { denb[i] += wi; numb[i] = fmaf(wi, pv.y, numb[i]); }
        }
    }
    // ---- m > l0+3 : forward for all 4 ----
    #pragma unroll 2
    for (int m = l0 + 4; m < LEN; ++m) {
        float2 pv = __ldg(hp + m*DIMN);
        float zc[4];
        #pragma unroll
        for (int i = 0; i < 4; i++) zc[i] = h1s[i] + pv.x;
        __half2 wa = hw_ex22(__hmul2(hw_tanh2(__floats2half2_rn(zc[0], zc[1])), kt2));
        __half2 wb = hw_ex22(__hmul2(hw_tanh2(__floats2half2_rn(zc[2], zc[3])), kt2));
        float2 w01 = __half22float2(wa), w23 = __half22float2(wb);
        float w[4] = {w01.x, w01.y, w23.x, w23.y};
        #pragma unroll
        for (int i = 0; i < 4; i++) {
            float wi = (zc[i] < 1e29f) ? w[i] : 0.0f;
            denf[i] += wi;
            numf[i] = fmaf(wi, pv.y, numf[i]);
        }
    }

    if (e < DIMN) {
        float hs = 0.0f;
        #pragma unroll
        for (int t = 0; t < 16; t++) hs += g_hsumP[(b*16 + t)*DIMN + e];
        hs *= 0.00390625f;   // /256, uniform-softmax fallback
        #pragma unroll
        for (int i = 0; i < 4; i++) {
            int idx = (b*LEN + l0 + i)*DIMN + e;
            g_sfw[idx] = (denf[i] > 0.0f) ? __fdividef(numf[i], denf[i]) : hs;
            g_sbw[idx] = (denb[i] > 0.0f) ? __fdividef(numb[i], denb[i]) : hs;
        }
    }
}

// ======================= final: reduce partials + MLP (one block per batch) ====
__global__ void __launch_bounds__(256) final_kernel(
    const float* __restrict__ F1_w, const float* __restrict__ F1_b,
    const float* __restrict__ F2_w, const float* __restrict__ F2_b,
    float* __restrict__ out)
{
    __shared__ float ss[D2];
    __shared__ float red[256];
    const int b   = blockIdx.x;
    const int tid = threadIdx.x;

    for (int e = tid; e < D2; e += 256) {
        float s = 0.0f;
        #pragma unroll
        for (int mt = 0; mt < 16; ++mt)
            s += g_part2[(b*16 + mt)*D2 + e];
        ss[e] = s;
    }
    __syncthreads();

    float v = 0.0f;
    if (tid < DIMN) {
        float acc = F1_b[tid];
        #pragma unroll 4
        for (int k = 0; k < D2; ++k)
            acc = fmaf(ss[k], F1_w[k*DIMN + tid], acc);
        acc = fmaxf(acc, 0.0f);
        v = acc * F2_w[tid];
    }
    red[tid] = v;
    __syncthreads();
    for (int s = 128; s > 0; s >>= 1) {
        if (tid < s) red[tid] += red[tid + s];
        __syncthreads();
    }
    if (tid == 0) out[b] = red[0] + F2_b[0];
}

// ======================= launch =======================
extern "C" void kernel_launch(void* const* d_in, const int* in_sizes, int n_in,
                              void* d_out, int out_size)
{
    const int*   x     = (const int*)  d_in[0];
    const float* emb   = (const float*)d_in[1];
    const float* Wh_w  = (const float*)d_in[2];
    const float* Wh_b  = (const float*)d_in[3];
    const float* W1_w  = (const float*)d_in[4];
    const float* W2_w  = (const float*)d_in[5];
    const float* batt  = (const float*)d_in[6];
    const float* cptr  = (const float*)d_in[7];
    const float* Wf1_w = (const float*)d_in[8];
    const float* Wf2_w = (const float*)d_in[9];
    const float* Wf2_b = (const float*)d_in[10];
    const float* Ws1_w = (const float*)d_in[11];
    const float* Ws1_b = (const float*)d_in[12];
    const float* Ws_w  = (const float*)d_in[13];
    const float* Ws_b  = (const float*)d_in[14];
    const float* F1_w  = (const float*)d_in[15];
    const float* F1_b  = (const float*)d_in[16];
    const float* F2_w  = (const float*)d_in[17];
    const float* F2_b  = (const float*)d_in[18];
    float* out = (float*)d_out;

    // G1: h = elu(xx @ Wh + b)
    gemm_k<0,DIMN,DIMN,32><<<dim3(NTOK/BM, 4), 128>>>(emb, Wh_w, nullptr, nullptr,
                                                      Wh_b, nullptr, x, emb, cptr);
    // G2: h1m / hpack / hf2c (+ hsum partials at y==12)
    gemm_k<1,DIMN,DIMN,32><<<dim3(NTOK/BM, 13), 128>>>(nullptr, W1_w, W2_w, Wf2_w,
                                                       batt, Wf2_b, x, emb, cptr);
    attn_kernel<<<dim3(LEN/4, BATCH), 224>>>(cptr);
    // G4: gates -> uu   (blockIdx.z = dir)
    gemm_k<2,DIMN,DIMN,32><<<dim3(NTOK/BM, 4, 2), 128>>>(nullptr, Wf1_w, nullptr, nullptr,
                                                         nullptr, nullptr, nullptr, nullptr, cptr);
    // G5: tmp = elu(uu @ Ws1 + b)
    gemm_k<3,D2,D2,32><<<dim3(NTOK/BM, 7), 128>>>(nullptr, Ws1_w, nullptr, nullptr,
                                                  Ws1_b, nullptr, nullptr, nullptr, cptr);
    // G6: att_s + partial s_s
    gemm_k<4,D2,D2,32><<<dim3(NTOK/BM, 7), 128>>>(nullptr, Ws_w, nullptr, nullptr,
                                                  Ws_b, nullptr, nullptr, nullptr, cptr);
    final_kernel<<<BATCH, 256>>>(F1_w, F1_b, F2_w, F2_b, out);
}

// round 11
// speedup vs baseline: 1.3258x; 1.3258x over previous
#include <cuda_runtime.h>
#include <cuda_fp16.h>

#define DIMN   200
#define LEN    256
#define BATCH  8
#define NTOK   (BATCH*LEN)      // 2048
#define D2     (2*DIMN)         // 400

// ---------------- scratch (static device memory; no allocations) ----------------
__device__ float  g_h    [NTOK*DIMN + 64];   // h, padded for attn e-overread
__device__ float  g_h1m  [NTOK*DIMN + 64];   // (h1+b)/c, mask-encoded (1e30), padded
__device__ float2 g_hpack[NTOK*DIMN + 64];   // {h2/c mask-encoded, h}, padded
__device__ float  g_hf2c [NTOK*DIMN];        // h @ Wf2_w + Wf2_b
__device__ float  g_sfw  [NTOK*DIMN];
__device__ float  g_sbw  [NTOK*DIMN];
__device__ float  g_hsumP[64*DIMN + 64];     // per-32-token-tile partial sums of h
__device__ float  g_uu   [NTOK*D2];          // [token][2D]
__device__ float  g_tmp  [NTOK*D2];          // elu(uu@Ws1+b)
__device__ float  g_part2[64*D2];            // per-Mtile partial of s_s

__device__ __forceinline__ float eluf(float a){ return a > 0.0f ? a : expm1f(a); }
__device__ __forceinline__ __half2 hw_tanh2(__half2 x){
    __half2 y; asm("tanh.approx.f16x2 %0, %1;" : "=r"(*(unsigned*)&y) : "r"(*(unsigned*)&x)); return y;
}
__device__ __forceinline__ __half2 hw_ex22(__half2 x){
    __half2 y; asm("ex2.approx.f16x2 %0, %1;" : "=r"(*(unsigned*)&y) : "r"(*(unsigned*)&x)); return y;
}

// ==== Tiled SGEMM, split-K-in-block (BM=32, BN=64, BK=16, 256 thr = 2 warpgroups,
//      4x4 microtile per 128-thread group; wg0 even k-tiles, wg1 odd k-tiles) ====
// MODE 0: h   = elu(gather(emb,x) @ Wh + Wh_b)                      -> g_h
// MODE 1: y<12: {W1(+batt,mask,/c), W2(mask,/c,pack h), Wf2(+b)};  y==12: hsum partials
// MODE 2: f = sigmoid(s_dir @ Wf1 + hf2c); uu = f*h+(1-f)*s         -> g_uu (dir=blockIdx.z)
// MODE 3: tmp = elu(uu @ Ws1 + Ws1_b)                               -> g_tmp
// MODE 4: att_s = tmp @ Ws + Ws_b; partial s_s = sum_rows uu*att_s  -> g_part2
#define BM 32
#define BN 64
#define BK 16

template<int MODE, int K, int N>
__global__ void __launch_bounds__(256) gemm_k(
    const float* __restrict__ A,
    const float* __restrict__ B0, const float* __restrict__ B1, const float* __restrict__ B2,
    const float* __restrict__ bias0, const float* __restrict__ bias2,
    const int* __restrict__ xidx, const float* __restrict__ emb,
    const float* __restrict__ cptr)
{
    const int tid = threadIdx.x;
    const int t0  = blockIdx.x * BM;

    // ---- hsum side-channel slice (MODE 1, y==12) ----
    if (MODE == 1 && blockIdx.y == 12) {
        for (int e = tid; e < DIMN; e += 256) {
            float s = 0.0f;
            #pragma unroll 4
            for (int j = 0; j < BM; ++j) s += g_h[(t0 + j)*DIMN + e];
            g_hsumP[blockIdx.x*DIMN + e] = s;
        }
        return;
    }

    __shared__ __align__(16) float As[2][BK][BM];
    __shared__ __align__(16) float Bs[2][BK][BN];
    __shared__ float Rd[128][17];               // cross-wg reduction (pad 17: conflict-free)
    __shared__ float red[8][BN];                // MODE 4 reduction

    const int tid128 = tid & 127;
    const int wg  = tid >> 7;       // warp-group 0/1
    const int tx  = tid128 & 15;    // cols tx*4
    const int ty  = tid128 >> 4;    // rows ty*4

    int n0, matid = 0;
    const float* B = B0;
    if (MODE == 1) {
        matid = blockIdx.y >> 2;
        n0 = (blockIdx.y & 3) * BN;
        B  = (matid == 0) ? B0 : (matid == 1) ? B1 : B2;
    } else {
        n0 = blockIdx.y * BN;
    }

    const float* Asrc;
    if      (MODE == 0) Asrc = A;
    else if (MODE == 1) Asrc = g_h;
    else if (MODE == 2) Asrc = blockIdx.z ? g_sbw : g_sfw;
    else if (MODE == 3) Asrc = g_uu;
    else                Asrc = g_tmp;

    // super-tile (32 k) load maps over 256 threads:
    // A 32x32: 1 float4/thread. B 32x64: 2 float4/thread (rows r and r+16).
    const int am   = tid >> 3;          // 0..31
    const int ak4  = (tid & 7) * 4;     // 0..28
    const int abuf = ak4 >> 4;          // which k-subtile buffer
    const int alk  = ak4 & 15;
    const int brow = tid >> 4;          // 0..15
    const int bn4  = (tid & 15) * 4;    // 0..60

    long arow;
    if (MODE == 0) arow = (long)__ldg(&xidx[t0 + am]) * K;
    else           arow = (long)(t0 + am) * K;

    const int gn_b = n0 + bn4;
    const bool bvalid = (gn_b < N);

    float acc[4][4];
    #pragma unroll
    for (int i = 0; i < 4; i++)
        #pragma unroll
        for (int j = 0; j < 4; j++) acc[i][j] = 0.0f;

    float4 av, bv0, bv1;
    auto loadSuper = [&](int k0) {
        int kq = k0 + ak4;
        av = make_float4(0,0,0,0);
        if (kq < K) av = *reinterpret_cast<const float4*>(Asrc + arow + kq);   // K%4==0
        int k1 = k0 + brow;
        int k2 = k0 + brow + 16;
        bv0 = make_float4(0,0,0,0);
        bv1 = make_float4(0,0,0,0);
        if (bvalid) {
            if (k1 < K) bv0 = *reinterpret_cast<const float4*>(B + (long)k1 * N + gn_b);
            if (k2 < K) bv1 = *reinterpret_cast<const float4*>(B + (long)k2 * N + gn_b);
        }
    };
    auto storeSuper = [&]() {
        As[abuf][alk+0][am] = av.x; As[abuf][alk+1][am] = av.y;
        As[abuf][alk+2][am] = av.z; As[abuf][alk+3][am] = av.w;
        *reinterpret_cast<float4*>(&Bs[0][brow][bn4]) = bv0;
        *reinterpret_cast<float4*>(&Bs[1][brow][bn4]) = bv1;
    };

    constexpr int T = (K + BK - 1) / BK;    // k-tiles (13 for K=200, 25 for K=400)
    constexpr int S = (T + 1) / 2;          // super-tiles

    loadSuper(0);
    storeSuper();
    __syncthreads();

    for (int s = 0; s < S; s++) {
        const bool more = (s + 1 < S);
        if (more) loadSuper((s + 1) * 32);

        if (2*s + wg < T) {    // my k-tile exists (zero-padded tail is safe)
            #pragma unroll
            for (int kk = 0; kk < BK; kk++) {
                float4 a4 = *reinterpret_cast<const float4*>(&As[wg][kk][ty*4]);
                float4 b4 = *reinterpret_cast<const float4*>(&Bs[wg][kk][tx*4]);
                float aa[4] = {a4.x,a4.y,a4.z,a4.w};
                float bb[4] = {b4.x,b4.y,b4.z,b4.w};
                #pragma unroll
                for (int i = 0; i < 4; i++)
                    #pragma unroll
                    for (int j = 0; j < 4; j++)
                        acc[i][j] = fmaf(aa[i], bb[j], acc[i][j]);
            }
        }
        __syncthreads();
        if (more) {
            storeSuper();
            __syncthreads();
        }
    }

    // ---- merge wg1 partials into wg0 ----
    if (wg == 1) {
        #pragma unroll
        for (int i = 0; i < 4; i++)
            #pragma unroll
            for (int j = 0; j < 4; j++)
                Rd[tid128][i*4 + j] = acc[i][j];
    }
    __syncthreads();
    if (wg == 0) {
        #pragma unroll
        for (int i = 0; i < 4; i++)
            #pragma unroll
            for (int j = 0; j < 4; j++)
                acc[i][j] += Rd[tid128][i*4 + j];
    }

    // ---------------- epilogues (wg0 only; logic identical to validated version) ---
    int  gcv[4]; bool ok[4]; float bj[4];
    #pragma unroll
    for (int j = 0; j < 4; j++) {
        gcv[j] = n0 + tx*4 + j;
        ok[j]  = gcv[j] < N;
    }

    if (MODE == 0) {
        if (wg == 0) {
            #pragma unroll
            for (int j = 0; j < 4; j++) bj[j] = ok[j] ? __ldg(&bias0[gcv[j]]) : 0.0f;
            #pragma unroll
            for (int i = 0; i < 4; i++) {
                int gt = t0 + ty*4 + i;
                #pragma unroll
                for (int j = 0; j < 4; j++)
                    if (ok[j]) g_h[gt*DIMN + gcv[j]] = eluf(acc[i][j] + bj[j]);
            }
        }
    }
    else if (MODE == 1) {
        if (wg == 0) {
            const float invc = 1.0f / __ldg(cptr);
            #pragma unroll
            for (int j = 0; j < 4; j++) {
                bj[j] = 0.0f;
                if (ok[j]) {
                    if (matid == 0) bj[j] = __ldg(&bias0[gcv[j]]);
                    if (matid == 2) bj[j] = __ldg(&bias2[gcv[j]]);
                }
            }
            #pragma unroll
            for (int i = 0; i < 4; i++) {
                int gt = t0 + ty*4 + i;
                long eoff = (long)__ldg(&xidx[gt]) * DIMN;
                #pragma unroll
                for (int j = 0; j < 4; j++) {
                    if (!ok[j]) continue;
                    if (matid == 0) {
                        bool mk = (__ldg(&emb[eoff + gcv[j]]) == 1.0f);
                        g_h1m[gt*DIMN + gcv[j]] = mk ? 1e30f : (acc[i][j] + bj[j]) * invc;
                    } else if (matid == 1) {
                        bool mk = (__ldg(&emb[eoff + gcv[j]]) == 1.0f);
                        float2 pp;
                        pp.x = mk ? 1e30f : acc[i][j] * invc;
                        pp.y = g_h[gt*DIMN + gcv[j]];
                        g_hpack[gt*DIMN + gcv[j]] = pp;
                    } else {
                        g_hf2c[gt*DIMN + gcv[j]] = acc[i][j] + bj[j];
                    }
                }
            }
        }
    }
    else if (MODE == 2) {
        if (wg == 0) {
            const int dir = blockIdx.z;
            #pragma unroll
            for (int i = 0; i < 4; i++) {
                int gt = t0 + ty*4 + i;
                #pragma unroll
                for (int j = 0; j < 4; j++) {
                    if (!ok[j]) continue;
                    int idx = gt*DIMN + gcv[j];
                    float f = 1.0f / (1.0f + __expf(-(acc[i][j] + g_hf2c[idx])));
                    float hh = g_h[idx];
                    float ss = Asrc[idx];
                    g_uu[gt*D2 + dir*DIMN + gcv[j]] = f*hh + (1.0f - f)*ss;
                }
            }
        }
    }
    else if (MODE == 3) {
        if (wg == 0) {
            #pragma unroll
            for (int j = 0; j < 4; j++) bj[j] = ok[j] ? __ldg(&bias0[gcv[j]]) : 0.0f;
            #pragma unroll
            for (int i = 0; i < 4; i++) {
                int gt = t0 + ty*4 + i;
                #pragma unroll
                for (int j = 0; j < 4; j++)
                    if (ok[j]) g_tmp[gt*D2 + gcv[j]] = eluf(acc[i][j] + bj[j]);
            }
        }
    }
    else { // MODE 4
        if (wg == 0) {
            #pragma unroll
            for (int j = 0; j < 4; j++) bj[j] = ok[j] ? __ldg(&bias0[gcv[j]]) : 0.0f;
            float pr[4] = {0,0,0,0};
            #pragma unroll
            for (int i = 0; i < 4; i++) {
                int gt = t0 + ty*4 + i;
                #pragma unroll
                for (int j = 0; j < 4; j++) {
                    if (!ok[j]) continue;
                    float att = acc[i][j] + bj[j];
                    pr[j] += g_uu[gt*D2 + gcv[j]] * att;
                }
            }
            #pragma unroll
            for (int j = 0; j < 4; j++) red[ty][tx*4 + j] = pr[j];
        }
        __syncthreads();
        if (tid < BN) {
            float s = 0.0f;
            #pragma unroll
            for (int r = 0; r < 8; r++) s += red[r][tid];
            int gc = n0 + tid;
            if (gc < N) g_part2[blockIdx.x*D2 + gc] = s;
        }
    }
}

// ======================= fused masked per-feature softmax attention ============
// block = (b, group of 4 l). thread = feature e. f16x2 MUFU (1 MUFU/element).
__global__ void __launch_bounds__(224) attn_kernel(const float* __restrict__ cptr)
{
    const int b  = blockIdx.y;
    const int l0 = blockIdx.x * 4;
    const int e  = threadIdx.x;

    const float C  = __ldg(cptr);
    const float ktf = C * 1.4426950408889634f;   // c*log2(e)
    const __half2 kt2 = __float2half2_rn(ktf);

    float h1s[4];
    #pragma unroll
    for (int i = 0; i < 4; i++) h1s[i] = g_h1m[(b*LEN + l0 + i)*DIMN + e];

    float denf[4] = {0,0,0,0}, numf[4] = {0,0,0,0};
    float denb[4] = {0,0,0,0}, numb[4] = {0,0,0,0};

    const float2* __restrict__ hp = g_hpack + (size_t)b*LEN*DIMN + e;

    // ---- m < l0 : backward for all 4 ----
    #pragma unroll 2
    for (int m = 0; m < l0; ++m) {
        float2 pv = __ldg(hp + m*DIMN);
        float zc[4];
        #pragma unroll
        for (int i = 0; i < 4; i++) zc[i] = h1s[i] + pv.x;
        __half2 wa = hw_ex22(__hmul2(hw_tanh2(__floats2half2_rn(zc[0], zc[1])), kt2));
        __half2 wb = hw_ex22(__hmul2(hw_tanh2(__floats2half2_rn(zc[2], zc[3])), kt2));
        float2 w01 = __half22float2(wa), w23 = __half22float2(wb);
        float w[4] = {w01.x, w01.y, w23.x, w23.y};
        #pragma unroll
        for (int i = 0; i < 4; i++) {
            float wi = (zc[i] < 1e29f) ? w[i] : 0.0f;
            denb[i] += wi;
            numb[i] = fmaf(wi, pv.y, numb[i]);
        }
    }
    // ---- edge iterations m = l0..l0+3 ----
    #pragma unroll
    for (int i2 = 0; i2 < 4; i2++) {
        float2 pv = __ldg(hp + (l0 + i2)*DIMN);
        float zc[4];
        #pragma unroll
        for (int i = 0; i < 4; i++) zc[i] = h1s[i] + pv.x;
        __half2 wa = hw_ex22(__hmul2(hw_tanh2(__floats2half2_rn(zc[0], zc[1])), kt2));
        __half2 wb = hw_ex22(__hmul2(hw_tanh2(__floats2half2_rn(zc[2], zc[3])), kt2));
        float2 w01 = __half22float2(wa), w23 = __half22float2(wb);
        float w[4] = {w01.x, w01.y, w23.x, w23.y};
        #pragma unroll
        for (int i = 0; i < 4; i++) {
            if (i == i2) continue;
            float wi = (zc[i] < 1e29f) ? w[i] : 0.0f;
            if (i < i2) { denf[i] += wi; numf[i] = fmaf(wi, pv.y, numf[i]); }
            else        { denb[i] += wi; numb[i] = fmaf(wi, pv.y, numb[i]); }
        }
    }
    // ---- m > l0+3 : forward for all 4 ----
    #pragma unroll 2
    for (int m = l0 + 4; m < LEN; ++m) {
        float2 pv = __ldg(hp + m*DIMN);
        float zc[4];
        #pragma unroll
        for (int i = 0; i < 4; i++) zc[i] = h1s[i] + pv.x;
        __half2 wa = hw_ex22(__hmul2(hw_tanh2(__floats2half2_rn(zc[0], zc[1])), kt2));
        __half2 wb = hw_ex22(__hmul2(hw_tanh2(__floats2half2_rn(zc[2], zc[3])), kt2));
        float2 w01 = __half22float2(wa), w23 = __half22float2(wb);
        float w[4] = {w01.x, w01.y, w23.x, w23.y};
        #pragma unroll
        for (int i = 0; i < 4; i++) {
            float wi = (zc[i] < 1e29f) ? w[i] : 0.0f;
            denf[i] += wi;
            numf[i] = fmaf(wi, pv.y, numf[i]);
        }
    }

    if (e < DIMN) {
        float hs = 0.0f;
        #pragma unroll
        for (int t = 0; t < 8; t++) hs += g_hsumP[(b*8 + t)*DIMN + e];
        hs *= 0.00390625f;   // /256, uniform-softmax fallback
        #pragma unroll
        for (int i = 0; i < 4; i++) {
            int idx = (b*LEN + l0 + i)*DIMN + e;
            g_sfw[idx] = (denf[i] > 0.0f) ? __fdividef(numf[i], denf[i]) : hs;
            g_sbw[idx] = (denb[i] > 0.0f) ? __fdividef(numb[i], denb[i]) : hs;
        }
    }
}

// ======================= final: reduce partials + MLP (one block per batch) ====
__global__ void __launch_bounds__(256) final_kernel(
    const float* __restrict__ F1_w, const float* __restrict__ F1_b,
    const float* __restrict__ F2_w, const float* __restrict__ F2_b,
    float* __restrict__ out)
{
    __shared__ float ss[D2];
    __shared__ float red[256];
    const int b   = blockIdx.x;
    const int tid = threadIdx.x;

    for (int e = tid; e < D2; e += 256) {
        float s = 0.0f;
        #pragma unroll
        for (int mt = 0; mt < 8; ++mt)
            s += g_part2[(b*8 + mt)*D2 + e];
        ss[e] = s;
    }
    __syncthreads();

    float v = 0.0f;
    if (tid < DIMN) {
        float acc = F1_b[tid];
        #pragma unroll 4
        for (int k = 0; k < D2; ++k)
            acc = fmaf(ss[k], F1_w[k*DIMN + tid], acc);
        acc = fmaxf(acc, 0.0f);
        v = acc * F2_w[tid];
    }
    red[tid] = v;
    __syncthreads();
    for (int s = 128; s > 0; s >>= 1) {
        if (tid < s) red[tid] += red[tid + s];
        __syncthreads();
    }
    if (tid == 0) out[b] = red[0] + F2_b[0];
}

// ======================= launch =======================
extern "C" void kernel_launch(void* const* d_in, const int* in_sizes, int n_in,
                              void* d_out, int out_size)
{
    const int*   x     = (const int*)  d_in[0];
    const float* emb   = (const float*)d_in[1];
    const float* Wh_w  = (const float*)d_in[2];
    const float* Wh_b  = (const float*)d_in[3];
    const float* W1_w  = (const float*)d_in[4];
    const float* W2_w  = (const float*)d_in[5];
    const float* batt  = (const float*)d_in[6];
    const float* cptr  = (const float*)d_in[7];
    const float* Wf1_w = (const float*)d_in[8];
    const float* Wf2_w = (const float*)d_in[9];
    const float* Wf2_b = (const float*)d_in[10];
    const float* Ws1_w = (const float*)d_in[11];
    const float* Ws1_b = (const float*)d_in[12];
    const float* Ws_w  = (const float*)d_in[13];
    const float* Ws_b  = (const float*)d_in[14];
    const float* F1_w  = (const float*)d_in[15];
    const float* F1_b  = (const float*)d_in[16];
    const float* F2_w  = (const float*)d_in[17];
    const float* F2_b  = (const float*)d_in[18];
    float* out = (float*)d_out;

    // G1: h = elu(xx @ Wh + b)
    gemm_k<0,DIMN,DIMN><<<dim3(NTOK/BM, 4), 256>>>(emb, Wh_w, nullptr, nullptr,
                                                   Wh_b, nullptr, x, emb, cptr);
    // G2: h1m / hpack / hf2c (+ hsum partials at y==12)
    gemm_k<1,DIMN,DIMN><<<dim3(NTOK/BM, 13), 256>>>(nullptr, W1_w, W2_w, Wf2_w,
                                                    batt, Wf2_b, x, emb, cptr);
    attn_kernel<<<dim3(LEN/4, BATCH), 224>>>(cptr);
    // G4: gates -> uu   (blockIdx.z = dir)
    gemm_k<2,DIMN,DIMN><<<dim3(NTOK/BM, 4, 2), 256>>>(nullptr, Wf1_w, nullptr, nullptr,
                                                      nullptr, nullptr, nullptr, nullptr, cptr);
    // G5: tmp = elu(uu @ Ws1 + b)
    gemm_k<3,D2,D2><<<dim3(NTOK/BM, 7), 256>>>(nullptr, Ws1_w, nullptr, nullptr,
                                               Ws1_b, nullptr, nullptr, nullptr, cptr);
    // G6: att_s + partial s_s
    gemm_k<4,D2,D2><<<dim3(NTOK/BM, 7), 256>>>(nullptr, Ws_w, nullptr, nullptr,
                                               Ws_b, nullptr, nullptr, nullptr, cptr);
    final_kernel<<<BATCH, 256>>>(F1_w, F1_b, F2_w, F2_b, out);
}

// round 12
// speedup vs baseline: 1.4226x; 1.0730x over previous
#include <cuda_runtime.h>
#include <cuda_fp16.h>

#define DIMN   200
#define LEN    256
#define BATCH  8
#define NTOK   (BATCH*LEN)      // 2048
#define D2     (2*DIMN)         // 400

// ---------------- scratch (static device memory; no allocations) ----------------
__device__ float  g_h    [NTOK*DIMN + 64];   // h, padded for attn e-overread
__device__ float  g_h1m  [NTOK*DIMN + 64];   // (h1+b)/c, mask-encoded (1e30), padded
__device__ float2 g_hpack[NTOK*DIMN + 64];   // {h2/c mask-encoded, h}, padded
__device__ float  g_hf2c [NTOK*DIMN];        // h @ Wf2_w + Wf2_b
__device__ float  g_sfw  [NTOK*DIMN];
__device__ float  g_sbw  [NTOK*DIMN];
__device__ float  g_hsumP[64*DIMN + 64];     // per-32-token-tile partial sums of h
__device__ float  g_uu   [NTOK*D2];          // [token][2D]
__device__ float  g_tmp  [NTOK*D2];          // elu(uu@Ws1+b)
__device__ float  g_part2[64*D2];            // per-Mtile partial of s_s

__device__ __forceinline__ float eluf(float a){ return a > 0.0f ? a : expm1f(a); }
__device__ __forceinline__ __half2 hw_tanh2(__half2 x){
    __half2 y; asm("tanh.approx.f16x2 %0, %1;" : "=r"(*(unsigned*)&y) : "r"(*(unsigned*)&x)); return y;
}
__device__ __forceinline__ __half2 hw_ex22(__half2 x){
    __half2 y; asm("ex2.approx.f16x2 %0, %1;" : "=r"(*(unsigned*)&y) : "r"(*(unsigned*)&x)); return y;
}
// ---- packed f32x2 (Blackwell): 2 MACs per issue slot ----
__device__ __forceinline__ unsigned long long pk2(float lo, float hi){
    unsigned long long r; asm("mov.b64 %0, {%1,%2};" : "=l"(r) : "f"(lo), "f"(hi)); return r;
}
__device__ __forceinline__ void fma2(unsigned long long& c, unsigned long long a, unsigned long long b){
    asm("fma.rn.f32x2 %0, %1, %2, %0;" : "+l"(c) : "l"(a), "l"(b));
}
__device__ __forceinline__ void unpk2(float& lo, float& hi, unsigned long long v){
    asm("mov.b64 {%0,%1}, %2;" : "=f"(lo), "=f"(hi) : "l"(v));
}

// ==== Tiled SGEMM (BM=32, BN=64, BK=BKT, 128 thr, 4x4 microtile, dbl-buffered,
//      FFMA2 packed inner product) ====
// MODE 0: h   = elu(gather(emb,x) @ Wh + Wh_b)                      -> g_h
// MODE 1: y<12: {W1(+batt,mask,/c), W2(mask,/c,pack h), Wf2(+b)};  y==12: hsum partials
// MODE 2: f = sigmoid(s_dir @ Wf1 + hf2c); uu = f*h+(1-f)*s         -> g_uu (dir=blockIdx.z)
// MODE 3: tmp = elu(uu @ Ws1 + Ws1_b)                               -> g_tmp
// MODE 4: att_s = tmp @ Ws + Ws_b; partial s_s = sum_rows uu*att_s  -> g_part2
#define BM 32
#define BN 64

template<int MODE, int K, int N, int BKT>
__global__ void __launch_bounds__(128) gemm_k(
    const float* __restrict__ A,
    const float* __restrict__ B0, const float* __restrict__ B1, const float* __restrict__ B2,
    const float* __restrict__ bias0, const float* __restrict__ bias2,
    const int* __restrict__ xidx, const float* __restrict__ emb,
    const float* __restrict__ cptr)
{
    const int tid = threadIdx.x;
    const int t0  = blockIdx.x * BM;

    // ---- hsum side-channel slice (MODE 1, y==12) ----
    if (MODE == 1 && blockIdx.y == 12) {
        for (int e = tid; e < DIMN; e += 128) {
            float s = 0.0f;
            #pragma unroll 4
            for (int j = 0; j < BM; ++j) s += g_h[(t0 + j)*DIMN + e];
            g_hsumP[blockIdx.x*DIMN + e] = s;
        }
        return;
    }

    constexpr int AR = BKT / 16;   // A float4s per thread
    constexpr int BR = BKT / 8;    // B float4s per thread

    __shared__ __align__(16) float As[2][BKT][BM];
    __shared__ __align__(16) float Bs[2][BKT][BN];
    __shared__ __align__(16) float red[8][BN];   // MODE 4 reduction

    const int tx  = tid & 15;       // col group 0..15 -> cols tx*4
    const int ty  = tid >> 4;       // row group 0..7  -> rows ty*4

    int n0, matid = 0;
    const float* B = B0;
    if (MODE == 1) {
        matid = blockIdx.y >> 2;
        n0 = (blockIdx.y & 3) * BN;
        B  = (matid == 0) ? B0 : (matid == 1) ? B1 : B2;
    } else {
        n0 = blockIdx.y * BN;
    }

    const float* Asrc;
    if      (MODE == 0) Asrc = A;
    else if (MODE == 1) Asrc = g_h;
    else if (MODE == 2) Asrc = blockIdx.z ? g_sbw : g_sfw;
    else if (MODE == 3) Asrc = g_uu;
    else                Asrc = g_tmp;

    // load mapping: A BMxBKT (128 thr, AR float4 each), B BKTxBN (128 thr, BR float4 each)
    const int am  = tid >> 2;           // 0..31
    const int ak  = (tid & 3) * 4;      // 0,4,8,12  (+16*r)
    const int bk  = tid >> 4;           // 0..7      (+8*r)
    const int bn  = (tid & 15) * 4;     // 0..60

    long arow;
    if (MODE == 0) arow = (long)__ldg(&xidx[t0 + am]) * K;
    else           arow = (long)(t0 + am) * K;

    const int gn_b = n0 + bn;
    const bool bvalid = (gn_b < N);

    // packed accumulators: row i, col-pair jp (cols 2*jp, 2*jp+1)
    unsigned long long acc2[4][2];
    #pragma unroll
    for (int i = 0; i < 4; i++) { acc2[i][0] = 0ULL; acc2[i][1] = 0ULL; }

    float4 av[AR], bv[BR];
    auto loadTile = [&](int k0) {
        #pragma unroll
        for (int r = 0; r < AR; r++) {
            int kq = k0 + ak + r*16;
            av[r] = make_float4(0,0,0,0);
            if (K % BKT == 0 || kq < K)
                av[r] = *reinterpret_cast<const float4*>(Asrc + arow + kq);
        }
        #pragma unroll
        for (int r = 0; r < BR; r++) {
            int kq = k0 + bk + r*8;
            bv[r] = make_float4(0,0,0,0);
            if (bvalid && (K % BKT == 0 || kq < K))
                bv[r] = *reinterpret_cast<const float4*>(B + (long)kq * N + gn_b);
        }
    };
    auto storeTile = [&](int p) {
        #pragma unroll
        for (int r = 0; r < AR; r++) {
            int kq = ak + r*16;
            As[p][kq+0][am]=av[r].x; As[p][kq+1][am]=av[r].y;
            As[p][kq+2][am]=av[r].z; As[p][kq+3][am]=av[r].w;
        }
        #pragma unroll
        for (int r = 0; r < BR; r++)
            *reinterpret_cast<float4*>(&Bs[p][bk + r*8][bn]) = bv[r];
    };

    // prologue
    loadTile(0);
    storeTile(0);
    __syncthreads();

    int p = 0;
    for (int k0 = 0; k0 < K; k0 += BKT) {
        const bool more = (k0 + BKT < K);
        if (more) loadTile(k0 + BKT);

        #pragma unroll
        for (int kk = 0; kk < BKT; kk++) {
            float4 a4 = *reinterpret_cast<const float4*>(&As[p][kk][ty*4]);
            float4 b4 = *reinterpret_cast<const float4*>(&Bs[p][kk][tx*4]);
            unsigned long long b01 = pk2(b4.x, b4.y);
            unsigned long long b23 = pk2(b4.z, b4.w);
            float aa[4] = {a4.x, a4.y, a4.z, a4.w};
            #pragma unroll
            for (int i = 0; i < 4; i++) {
                unsigned long long ai = pk2(aa[i], aa[i]);
                fma2(acc2[i][0], ai, b01);
                fma2(acc2[i][1], ai, b23);
            }
        }

        if (more) {
            storeTile(p^1);
            __syncthreads();
            p ^= 1;
        }
    }

    // unpack to legacy acc[4][4]
    float acc[4][4];
    #pragma unroll
    for (int i = 0; i < 4; i++) {
        unpk2(acc[i][0], acc[i][1], acc2[i][0]);
        unpk2(acc[i][2], acc[i][3], acc2[i][1]);
    }

    // ---------------- epilogues (unchanged, validated) ----------------
    int  gcv[4]; bool ok[4]; float bj[4];
    #pragma unroll
    for (int j = 0; j < 4; j++) {
        gcv[j] = n0 + tx*4 + j;
        ok[j]  = gcv[j] < N;
    }

    if (MODE == 0) {
        #pragma unroll
        for (int j = 0; j < 4; j++) bj[j] = ok[j] ? __ldg(&bias0[gcv[j]]) : 0.0f;
        #pragma unroll
        for (int i = 0; i < 4; i++) {
            int gt = t0 + ty*4 + i;
            #pragma unroll
            for (int j = 0; j < 4; j++)
                if (ok[j]) g_h[gt*DIMN + gcv[j]] = eluf(acc[i][j] + bj[j]);
        }
    }
    else if (MODE == 1) {
        const float invc = 1.0f / __ldg(cptr);
        #pragma unroll
        for (int j = 0; j < 4; j++) {
            bj[j] = 0.0f;
            if (ok[j]) {
                if (matid == 0) bj[j] = __ldg(&bias0[gcv[j]]);
                if (matid == 2) bj[j] = __ldg(&bias2[gcv[j]]);
            }
        }
        #pragma unroll
        for (int i = 0; i < 4; i++) {
            int gt = t0 + ty*4 + i;
            long eoff = (long)__ldg(&xidx[gt]) * DIMN;
            #pragma unroll
            for (int j = 0; j < 4; j++) {
                if (!ok[j]) continue;
                if (matid == 0) {
                    bool mk = (__ldg(&emb[eoff + gcv[j]]) == 1.0f);
                    g_h1m[gt*DIMN + gcv[j]] = mk ? 1e30f : (acc[i][j] + bj[j]) * invc;
                } else if (matid == 1) {
                    bool mk = (__ldg(&emb[eoff + gcv[j]]) == 1.0f);
                    float2 pp;
                    pp.x = mk ? 1e30f : acc[i][j] * invc;
                    pp.y = g_h[gt*DIMN + gcv[j]];
                    g_hpack[gt*DIMN + gcv[j]] = pp;
                } else {
                    g_hf2c[gt*DIMN + gcv[j]] = acc[i][j] + bj[j];
                }
            }
        }
    }
    else if (MODE == 2) {
        const int dir = blockIdx.z;
        #pragma unroll
        for (int i = 0; i < 4; i++) {
            int gt = t0 + ty*4 + i;
            #pragma unroll
            for (int j = 0; j < 4; j++) {
                if (!ok[j]) continue;
                int idx = gt*DIMN + gcv[j];
                float f = 1.0f / (1.0f + __expf(-(acc[i][j] + g_hf2c[idx])));
                float hh = g_h[idx];
                float ss = Asrc[idx];
                g_uu[gt*D2 + dir*DIMN + gcv[j]] = f*hh + (1.0f - f)*ss;
            }
        }
    }
    else if (MODE == 3) {
        #pragma unroll
        for (int j = 0; j < 4; j++) bj[j] = ok[j] ? __ldg(&bias0[gcv[j]]) : 0.0f;
        #pragma unroll
        for (int i = 0; i < 4; i++) {
            int gt = t0 + ty*4 + i;
            #pragma unroll
            for (int j = 0; j < 4; j++)
                if (ok[j]) g_tmp[gt*D2 + gcv[j]] = eluf(acc[i][j] + bj[j]);
        }
    }
    else { // MODE 4
        #pragma unroll
        for (int j = 0; j < 4; j++) bj[j] = ok[j] ? __ldg(&bias0[gcv[j]]) : 0.0f;
        float pr[4] = {0,0,0,0};
        #pragma unroll
        for (int i = 0; i < 4; i++) {
            int gt = t0 + ty*4 + i;
            #pragma unroll
            for (int j = 0; j < 4; j++) {
                if (!ok[j]) continue;
                float att = acc[i][j] + bj[j];
                pr[j] += g_uu[gt*D2 + gcv[j]] * att;
            }
        }
        __syncthreads();
        #pragma unroll
        for (int j = 0; j < 4; j++) red[ty][tx*4 + j] = pr[j];
        __syncthreads();
        if (tid < BN) {
            float s = 0.0f;
            #pragma unroll
            for (int r = 0; r < 8; r++) s += red[r][tid];
            int gc = n0 + tid;
            if (gc < N) g_part2[blockIdx.x*D2 + gc] = s;
        }
    }
}

// ======================= fused masked per-feature softmax attention ============
// block = (b, group of 4 l). thread = feature e. f16x2 MUFU (1 MUFU/element).
__global__ void __launch_bounds__(224) attn_kernel(const float* __restrict__ cptr)
{
    const int b  = blockIdx.y;
    const int l0 = blockIdx.x * 4;
    const int e  = threadIdx.x;

    const float C  = __ldg(cptr);
    const float ktf = C * 1.4426950408889634f;   // c*log2(e)
    const __half2 kt2 = __float2half2_rn(ktf);

    float h1s[4];
    #pragma unroll
    for (int i = 0; i < 4; i++) h1s[i] = g_h1m[(b*LEN + l0 + i)*DIMN + e];

    float denf[4] = {0,0,0,0}, numf[4] = {0,0,0,0};
    float denb[4] = {0,0,0,0}, numb[4] = {0,0,0,0};

    const float2* __restrict__ hp = g_hpack + (size_t)b*LEN*DIMN + e;

    // ---- m < l0 : backward for all 4 ----
    #pragma unroll 2
    for (int m = 0; m < l0; ++m) {
        float2 pv = __ldg(hp + m*DIMN);
        float zc[4];
        #pragma unroll
        for (int i = 0; i < 4; i++) zc[i] = h1s[i] + pv.x;
        __half2 wa = hw_ex22(__hmul2(hw_tanh2(__floats2half2_rn(zc[0], zc[1])), kt2));
        __half2 wb = hw_ex22(__hmul2(hw_tanh2(__floats2half2_rn(zc[2], zc[3])), kt2));
        float2 w01 = __half22float2(wa), w23 = __half22float2(wb);
        float w[4] = {w01.x, w01.y, w23.x, w23.y};
        #pragma unroll
        for (int i = 0; i < 4; i++) {
            float wi = (zc[i] < 1e29f) ? w[i] : 0.0f;
            denb[i] += wi;
            numb[i] = fmaf(wi, pv.y, numb[i]);
        }
    }
    // ---- edge iterations m = l0..l0+3 ----
    #pragma unroll
    for (int i2 = 0; i2 < 4; i2++) {
        float2 pv = __ldg(hp + (l0 + i2)*DIMN);
        float zc[4];
        #pragma unroll
        for (int i = 0; i < 4; i++) zc[i] = h1s[i] + pv.x;
        __half2 wa = hw_ex22(__hmul2(hw_tanh2(__floats2half2_rn(zc[0], zc[1])), kt2));
        __half2 wb = hw_ex22(__hmul2(hw_tanh2(__floats2half2_rn(zc[2], zc[3])), kt2));
        float2 w01 = __half22float2(wa), w23 = __half22float2(wb);
        float w[4] = {w01.x, w01.y, w23.x, w23.y};
        #pragma unroll
        for (int i = 0; i < 4; i++) {
            if (i == i2) continue;
            float wi = (zc[i] < 1e29f) ? w[i] : 0.0f;
            if (i < i2) { denf[i] += wi; numf[i] = fmaf(wi, pv.y, numf[i]); }
            else        { denb[i] += wi; numb[i] = fmaf(wi, pv.y, numb[i]); }
        }
    }
    // ---- m > l0+3 : forward for all 4 ----
    #pragma unroll 2
    for (int m = l0 + 4; m < LEN; ++m) {
        float2 pv = __ldg(hp + m*DIMN);
        float zc[4];
        #pragma unroll
        for (int i = 0; i < 4; i++) zc[i] = h1s[i] + pv.x;
        __half2 wa = hw_ex22(__hmul2(hw_tanh2(__floats2half2_rn(zc[0], zc[1])), kt2));
        __half2 wb = hw_ex22(__hmul2(hw_tanh2(__floats2half2_rn(zc[2], zc[3])), kt2));
        float2 w01 = __half22float2(wa), w23 = __half22float2(wb);
        float w[4] = {w01.x, w01.y, w23.x, w23.y};
        #pragma unroll
        for (int i = 0; i < 4; i++) {
            float wi = (zc[i] < 1e29f) ? w[i] : 0.0f;
            denf[i] += wi;
            numf[i] = fmaf(wi, pv.y, numf[i]);
        }
    }

    if (e < DIMN) {
        float hs = 0.0f;
        #pragma unroll
        for (int t = 0; t < 8; t++) hs += g_hsumP[(b*8 + t)*DIMN + e];
        hs *= 0.00390625f;   // /256, uniform-softmax fallback
        #pragma unroll
        for (int i = 0; i < 4; i++) {
            int idx = (b*LEN + l0 + i)*DIMN + e;
            g_sfw[idx] = (denf[i] > 0.0f) ? __fdividef(numf[i], denf[i]) : hs;
            g_sbw[idx] = (denb[i] > 0.0f) ? __fdividef(numb[i], denb[i]) : hs;
        }
    }
}

// ======================= final: reduce partials + MLP (one block per batch) ====
__global__ void __launch_bounds__(256) final_kernel(
    const float* __restrict__ F1_w, const float* __restrict__ F1_b,
    const float* __restrict__ F2_w, const float* __restrict__ F2_b,
    float* __restrict__ out)
{
    __shared__ float ss[D2];
    __shared__ float red[256];
    const int b   = blockIdx.x;
    const int tid = threadIdx.x;

    for (int e = tid; e < D2; e += 256) {
        float s = 0.0f;
        #pragma unroll
        for (int mt = 0; mt < 8; ++mt)
            s += g_part2[(b*8 + mt)*D2 + e];
        ss[e] = s;
    }
    __syncthreads();

    float v = 0.0f;
    if (tid < DIMN) {
        float acc = F1_b[tid];
        #pragma unroll 4
        for (int k = 0; k < D2; ++k)
            acc = fmaf(ss[k], F1_w[k*DIMN + tid], acc);
        acc = fmaxf(acc, 0.0f);
        v = acc * F2_w[tid];
    }
    red[tid] = v;
    __syncthreads();
    for (int s = 128; s > 0; s >>= 1) {
        if (tid < s) red[tid] += red[tid + s];
        __syncthreads();
    }
    if (tid == 0) out[b] = red[0] + F2_b[0];
}

// ======================= launch =======================
extern "C" void kernel_launch(void* const* d_in, const int* in_sizes, int n_in,
                              void* d_out, int out_size)
{
    const int*   x     = (const int*)  d_in[0];
    const float* emb   = (const float*)d_in[1];
    const float* Wh_w  = (const float*)d_in[2];
    const float* Wh_b  = (const float*)d_in[3];
    const float* W1_w  = (const float*)d_in[4];
    const float* W2_w  = (const float*)d_in[5];
    const float* batt  = (const float*)d_in[6];
    const float* cptr  = (const float*)d_in[7];
    const float* Wf1_w = (const float*)d_in[8];
    const float* Wf2_w = (const float*)d_in[9];
    const float* Wf2_b = (const float*)d_in[10];
    const float* Ws1_w = (const float*)d_in[11];
    const float* Ws1_b = (const float*)d_in[12];
    const float* Ws_w  = (const float*)d_in[13];
    const float* Ws_b  = (const float*)d_in[14];
    const float* F1_w  = (const float*)d_in[15];
    const float* F1_b  = (const float*)d_in[16];
    const float* F2_w  = (const float*)d_in[17];
    const float* F2_b  = (const float*)d_in[18];
    float* out = (float*)d_out;

    // G1: h = elu(xx @ Wh + b)
    gemm_k<0,DIMN,DIMN,16><<<dim3(NTOK/BM, 4), 128>>>(emb, Wh_w, nullptr, nullptr,
                                                      Wh_b, nullptr, x, emb, cptr);
    // G2: h1m / hpack / hf2c (+ hsum partials at y==12)
    gemm_k<1,DIMN,DIMN,16><<<dim3(NTOK/BM, 13), 128>>>(nullptr, W1_w, W2_w, Wf2_w,
                                                       batt, Wf2_b, x, emb, cptr);
    attn_kernel<<<dim3(LEN/4, BATCH), 224>>>(cptr);
    // G4: gates -> uu   (blockIdx.z = dir)
    gemm_k<2,DIMN,DIMN,16><<<dim3(NTOK/BM, 4, 2), 128>>>(nullptr, Wf1_w, nullptr, nullptr,
                                                         nullptr, nullptr, nullptr, nullptr, cptr);
    // G5: tmp = elu(uu @ Ws1 + b)
    gemm_k<3,D2,D2,32><<<dim3(NTOK/BM, 7), 128>>>(nullptr, Ws1_w, nullptr, nullptr,
                                                  Ws1_b, nullptr, nullptr, nullptr, cptr);
    // G6: att_s + partial s_s
    gemm_k<4,D2,D2,32><<<dim3(NTOK/BM, 7), 128>>>(nullptr, Ws_w, nullptr, nullptr,
                                                  Ws_b, nullptr, nullptr, nullptr, cptr);
    final_kernel<<<BATCH, 256>>>(F1_w, F1_b, F2_w, F2_b, out);
}